// round 1
// baseline (speedup 1.0000x reference)
#include <cuda_runtime.h>
#include <cstdint>

// Problem constants (fixed by the dataset)
#define BS_  8
#define N_   4096
#define B_   8
#define R_   64
#define D_   256

#define TOK        16                 // tokens per tile
#define CHUNKS     16                 // token chunks per (s,b) pair
#define TOK_PER_BLK (N_/CHUNKS)       // 256
#define TILES      (TOK_PER_BLK/TOK)  // 16
#define THREADS    256

// Padded shared-memory row strides (floats / float4-units)
#define ROWF  260                     // 256 + 4 pad, keeps 16B alignment (1040B)
#define ROW4  65
#define WSROW 65

// smem layout (floats):
//   Ks[64*260] Vs[64*260] qs[16*260] ms[16*260] ws[16*65] part[16*17] invs[16] sa[64]
#define SM_K    0
#define SM_V    (SM_K + R_*ROWF)
#define SM_Q    (SM_V + R_*ROWF)
#define SM_M    (SM_Q + TOK*ROWF)
#define SM_W    (SM_M + TOK*ROWF)
#define SM_P    (SM_W + TOK*WSROW)
#define SM_INV  (SM_P + TOK*17)
#define SM_A    (SM_INV + TOK)
#define SM_FLOATS (SM_A + R_)
#define SMEM_BYTES (SM_FLOATS * 4)

// ---- packed fp32x2 helpers (sm_103a FFMA2 path) ----
__device__ __forceinline__ unsigned long long pk2(float lo, float hi) {
    unsigned long long r;
    asm("mov.b64 %0, {%1,%2};" : "=l"(r) : "f"(lo), "f"(hi));
    return r;
}
__device__ __forceinline__ void upk2(unsigned long long v, float& lo, float& hi) {
    asm("mov.b64 {%0,%1}, %2;" : "=f"(lo), "=f"(hi) : "l"(v));
}
__device__ __forceinline__ void ffma2(unsigned long long& d,
                                      unsigned long long a,
                                      unsigned long long b) {
    asm("fma.rn.f32x2 %0, %1, %2, %0;" : "+l"(d) : "l"(a), "l"(b));
}

__global__ __launch_bounds__(THREADS, 1)
void ProceduralMemory_81535659147884_kernel(
    const float* __restrict__ q,
    const float* __restrict__ pm_K,
    const float* __restrict__ pm_V,
    const float* __restrict__ pm_a,
    float* __restrict__ out)
{
    extern __shared__ float sm[];
    float* Ks   = sm + SM_K;
    float* Vs   = sm + SM_V;
    float* qs   = sm + SM_Q;
    float* ms   = sm + SM_M;
    float* ws   = sm + SM_W;
    float* part = sm + SM_P;
    float* invs = sm + SM_INV;
    float* sa   = sm + SM_A;

    const int tid   = threadIdx.x;
    const int pair  = blockIdx.x / CHUNKS;     // 0..63
    const int chunk = blockIdx.x % CHUNKS;     // 0..15
    const int s = pair / B_;
    const int b = pair % B_;

    // ---- Stage K, V, a for this (s,b) pair (coalesced float4) ----
    {
        const float4* Kg = (const float4*)(pm_K + (size_t)pair * R_ * D_);
        const float4* Vg = (const float4*)(pm_V + (size_t)pair * R_ * D_);
        float4* Ks4 = (float4*)Ks;
        float4* Vs4 = (float4*)Vs;
        #pragma unroll
        for (int k = 0; k < (R_ * D_ / 4) / THREADS; ++k) {  // 16 iters
            int idx = tid + k * THREADS;
            int row = idx >> 6;          // /64 float4 per row
            int c4  = idx & 63;
            Ks4[row * ROW4 + c4] = Kg[idx];
            Vs4[row * ROW4 + c4] = Vg[idx];
        }
        if (tid < R_) sa[tid] = pm_a[(size_t)pair * R_ + tid];
    }

    for (int tile = 0; tile < TILES; ++tile) {
        const int n0 = chunk * TOK_PER_BLK + tile * TOK;

        // ---- Load q tile [16,256] (coalesced per-token 1KB segments) ----
        {
            const float4* qg = (const float4*)q;
            float4* qs4 = (float4*)qs;
            #pragma unroll
            for (int k = 0; k < 4; ++k) {
                int idx = tid + k * THREADS;         // 0..1023
                int t   = idx >> 6;
                int c4  = idx & 63;
                size_t g = (((size_t)s * N_ + (n0 + t)) * B_ + b) * (D_ / 4) + c4;
                qs4[t * ROW4 + c4] = qg[g];
            }
        }
        __syncthreads();   // also orders K/V staging on first tile

        // ---- sum of squares per token ----
        {
            int t = tid >> 4, seg = tid & 15;
            const float* p = qs + t * ROWF + seg * 16;
            float ssum = 0.f;
            #pragma unroll
            for (int i = 0; i < 16; ++i) ssum += p[i] * p[i];
            part[t * 17 + seg] = ssum;
        }
        __syncthreads();
        if (tid < TOK) {
            float ss = 0.f;
            #pragma unroll
            for (int i = 0; i < 16; ++i) ss += part[tid * 17 + i];
            float nrm = sqrtf(ss);
            invs[tid] = 1.0f / fmaxf(nrm, 1e-8f);
        }
        __syncthreads();

        // ---- Phase 1: scores[t][r] = (q . K_r) * invn[t] * a[r] ----
        {
            const int t  = tid & 15;
            const int r0 = (tid >> 4) * 4;           // 4 r-rows per thread
            const ulonglong2* q2 = (const ulonglong2*)(qs + t * ROWF);
            const ulonglong2* k0 = (const ulonglong2*)(Ks + (r0 + 0) * ROWF);
            const ulonglong2* k1 = (const ulonglong2*)(Ks + (r0 + 1) * ROWF);
            const ulonglong2* k2 = (const ulonglong2*)(Ks + (r0 + 2) * ROWF);
            const ulonglong2* k3 = (const ulonglong2*)(Ks + (r0 + 3) * ROWF);
            unsigned long long a0 = 0ull, a1 = 0ull, a2 = 0ull, a3 = 0ull;
            #pragma unroll 8
            for (int dv = 0; dv < D_ / 4; ++dv) {    // 64 iters, 4 floats each
                ulonglong2 qv = q2[dv];
                ulonglong2 v0 = k0[dv];
                ulonglong2 v1 = k1[dv];
                ulonglong2 v2 = k2[dv];
                ulonglong2 v3 = k3[dv];
                ffma2(a0, qv.x, v0.x); ffma2(a1, qv.x, v1.x);
                ffma2(a2, qv.x, v2.x); ffma2(a3, qv.x, v3.x);
                ffma2(a0, qv.y, v0.y); ffma2(a1, qv.y, v1.y);
                ffma2(a2, qv.y, v2.y); ffma2(a3, qv.y, v3.y);
            }
            const float inv = invs[t];
            float lo, hi;
            upk2(a0, lo, hi); ws[t * WSROW + r0 + 0] = (lo + hi) * inv * sa[r0 + 0];
            upk2(a1, lo, hi); ws[t * WSROW + r0 + 1] = (lo + hi) * inv * sa[r0 + 1];
            upk2(a2, lo, hi); ws[t * WSROW + r0 + 2] = (lo + hi) * inv * sa[r0 + 2];
            upk2(a3, lo, hi); ws[t * WSROW + r0 + 3] = (lo + hi) * inv * sa[r0 + 3];
        }
        __syncthreads();

        // ---- Phase 2: mod[t][d] = sum_r w[t][r] * V[r][d];  out = q*mod -> ms ----
        {
            const int t    = tid & 15;
            const int dblk = tid >> 4;               // 16 d-values per thread
            unsigned long long acc[8];
            #pragma unroll
            for (int i = 0; i < 8; ++i) acc[i] = 0ull;
            const float* wsr = ws + t * WSROW;
            const ulonglong2* Vb = (const ulonglong2*)Vs + dblk * 4;
            #pragma unroll 4
            for (int rr = 0; rr < R_; ++rr) {
                float w = wsr[rr];
                unsigned long long w2 = pk2(w, w);
                const ulonglong2* vr = Vb + rr * ROW4;
                #pragma unroll
                for (int i = 0; i < 4; ++i) {
                    ulonglong2 v = vr[i];
                    ffma2(acc[2 * i + 0], w2, v.x);
                    ffma2(acc[2 * i + 1], w2, v.y);
                }
            }
            const float4* qs4 = (const float4*)(qs + t * ROWF) + dblk * 4;
            float4* ms4 = (float4*)(ms + t * ROWF) + dblk * 4;
            #pragma unroll
            for (int i = 0; i < 4; ++i) {
                float4 qv = qs4[i];
                float m0, m1, m2, m3;
                upk2(acc[2 * i + 0], m0, m1);
                upk2(acc[2 * i + 1], m2, m3);
                float4 o;
                o.x = qv.x * m0; o.y = qv.y * m1;
                o.z = qv.z * m2; o.w = qv.w * m3;
                ms4[i] = o;
            }
        }
        __syncthreads();

        // ---- Coalesced store of the tile ----
        {
            float4* og = (float4*)out;
            const float4* ms4 = (const float4*)ms;
            #pragma unroll
            for (int k = 0; k < 4; ++k) {
                int idx = tid + k * THREADS;
                int t   = idx >> 6;
                int c4  = idx & 63;
                size_t g = (((size_t)s * N_ + (n0 + t)) * B_ + b) * (D_ / 4) + c4;
                og[g] = ms4[t * ROW4 + c4];
            }
        }
        // next tile's q-load is ordered by the barrier at its top
    }
}

extern "C" void kernel_launch(void* const* d_in, const int* in_sizes, int n_in,
                              void* d_out, int out_size)
{
    const float* q    = (const float*)d_in[0];
    const float* pm_K = (const float*)d_in[1];
    const float* pm_V = (const float*)d_in[2];
    const float* pm_a = (const float*)d_in[3];
    float* out = (float*)d_out;

    cudaFuncSetAttribute(ProceduralMemory_81535659147884_kernel,
                         cudaFuncAttributeMaxDynamicSharedMemorySize, SMEM_BYTES);

    dim3 grid(BS_ * B_ * CHUNKS);     // 1024 blocks
    ProceduralMemory_81535659147884_kernel<<<grid, THREADS, SMEM_BYTES>>>(
        q, pm_K, pm_V, pm_a, out);
}

// round 3
// speedup vs baseline: 2.3808x; 2.3808x over previous
#include <cuda_runtime.h>
#include <cuda_bf16.h>
#include <cstdint>

#define BS_  8
#define N_   4096
#define B_   8
#define R_   64
#define D_   256

#define MTILE   128
#define THREADS 256
#define ROWB    528        // bytes per smem row: 264 bf16 (256 data + 8 pad)

// ---- smem layout (bytes) ----
#define SMO_AHI  0                        // q hi  [128][264] bf16
#define SMO_ALO  (128*ROWB)               // q lo
#define SMO_BHI  (2*128*ROWB)             // K/V hi [64][264]
#define SMO_BLO  (SMO_BHI + 64*ROWB)
#define SMO_PART (SMO_BLO + 64*ROWB)      // 256 floats ssq partials
#define SMO_INV  (SMO_PART + 1024)        // 128 floats
#define SMO_SA   (SMO_INV + 512)          // 64 floats pm_a
#define SMEM_TOTAL (SMO_SA + 256)         // 204544 B

__device__ __forceinline__ uint32_t smem_u32(const void* p) {
    uint32_t a;
    asm("{ .reg .u64 t; cvta.to.shared.u64 t, %1; cvt.u32.u64 %0, t; }" : "=r"(a) : "l"(p));
    return a;
}
__device__ __forceinline__ void ldsm4(uint32_t* r, uint32_t addr) {
    asm volatile("ldmatrix.sync.aligned.m8n8.x4.shared.b16 {%0,%1,%2,%3}, [%4];"
                 : "=r"(r[0]), "=r"(r[1]), "=r"(r[2]), "=r"(r[3]) : "r"(addr));
}
__device__ __forceinline__ void ldsm4t(uint32_t* r, uint32_t addr) {
    asm volatile("ldmatrix.sync.aligned.m8n8.x4.trans.shared.b16 {%0,%1,%2,%3}, [%4];"
                 : "=r"(r[0]), "=r"(r[1]), "=r"(r[2]), "=r"(r[3]) : "r"(addr));
}
__device__ __forceinline__ void mma16816(float* c, const uint32_t* a, const uint32_t* b) {
    asm volatile("mma.sync.aligned.m16n8k16.row.col.f32.bf16.bf16.f32 "
                 "{%0,%1,%2,%3}, {%4,%5,%6,%7}, {%8,%9}, {%0,%1,%2,%3};"
                 : "+f"(c[0]), "+f"(c[1]), "+f"(c[2]), "+f"(c[3])
                 : "r"(a[0]), "r"(a[1]), "r"(a[2]), "r"(a[3]), "r"(b[0]), "r"(b[1]));
}
__device__ __forceinline__ uint32_t packbf(float x, float y) {
    __nv_bfloat162 h = __floats2bfloat162_rn(x, y);
    return *(uint32_t*)&h;
}
__device__ __forceinline__ void split4(float4 v, uint2& hi, uint2& lo) {
    __nv_bfloat16 hx = __float2bfloat16_rn(v.x), hy = __float2bfloat16_rn(v.y);
    __nv_bfloat16 hz = __float2bfloat16_rn(v.z), hw = __float2bfloat16_rn(v.w);
    hi.x = (uint32_t)__bfloat16_as_ushort(hx) | ((uint32_t)__bfloat16_as_ushort(hy) << 16);
    hi.y = (uint32_t)__bfloat16_as_ushort(hz) | ((uint32_t)__bfloat16_as_ushort(hw) << 16);
    lo.x = packbf(v.x - __bfloat162float(hx), v.y - __bfloat162float(hy));
    lo.y = packbf(v.z - __bfloat162float(hz), v.w - __bfloat162float(hw));
}

// GEMM2 pass: acc[8][4] += A(regs) x V(smem, ldmatrix.trans). bbase points at
// this pass' V buffer + per-lane offset + chunk d-offset.
__device__ __forceinline__ void gemm2_pass(float (&acc)[8][4],
                                           const uint32_t (&A)[4][4],
                                           uint32_t bbase) {
    #pragma unroll
    for (int k = 0; k < 4; ++k) {
        #pragma unroll
        for (int g = 0; g < 4; ++g) {
            uint32_t bb[4];
            ldsm4t(bb, bbase + (uint32_t)k * (16u * ROWB) + (uint32_t)g * 32u);
            mma16816(acc[2 * g + 0], A[k], bb + 0);
            mma16816(acc[2 * g + 1], A[k], bb + 2);
        }
    }
}

__global__ __launch_bounds__(THREADS, 1)
void ProceduralMemory_81535659147884_kernel(
    const float* __restrict__ q,
    const float* __restrict__ pm_K,
    const float* __restrict__ pm_V,
    const float* __restrict__ pm_a,
    float* __restrict__ out)
{
    extern __shared__ char smc[];
    const uint32_t smb = smem_u32(smc);

    const int tid  = threadIdx.x;
    const int wid  = tid >> 5;
    const int lane = tid & 31;

    const int pair = blockIdx.x >> 5;          // 0..63
    const int tile = blockIdx.x & 31;          // 0..31
    const int s = pair >> 3, b = pair & 7;
    const int n0 = tile * MTILE;

    float* partS = (float*)(smc + SMO_PART);
    float* invS  = (float*)(smc + SMO_INV);
    float* saS   = (float*)(smc + SMO_SA);

    // ---- Load + split q tile [128,256]: ssq partials + bf16 hi/lo to smem ----
    {
        const int h  = wid & 1;
        const int wr = wid >> 1;
        const int f4 = h * 32 + lane;
        const size_t base4 = ((size_t)(s * N_ + n0) * B_ + b) * (D_ / 4);
        const float4* qg = (const float4*)q;
        #pragma unroll 4
        for (int k = 0; k < 32; ++k) {
            int m = 4 * k + wr;
            float4 v = qg[base4 + (size_t)m * (B_ * D_ / 4) + f4];
            float ss = v.x * v.x + v.y * v.y + v.z * v.z + v.w * v.w;
            #pragma unroll
            for (int o = 16; o; o >>= 1) ss += __shfl_xor_sync(0xFFFFFFFFu, ss, o);
            if (lane == 0) partS[m * 2 + h] = ss;
            uint2 hi, lo; split4(v, hi, lo);
            uint32_t a1 = (uint32_t)m * ROWB + (uint32_t)f4 * 8u;
            *(uint2*)(smc + SMO_AHI + a1) = hi;
            *(uint2*)(smc + SMO_ALO + a1) = lo;
        }
    }
    // ---- Load + split K [64,256] ----
    {
        const int h  = wid & 1;
        const int wr = wid >> 1;
        const int f4 = h * 32 + lane;
        const float4* kg = (const float4*)pm_K + (size_t)pair * (R_ * D_ / 4);
        #pragma unroll 4
        for (int k = 0; k < 16; ++k) {
            int r = 4 * k + wr;
            float4 v = kg[(size_t)r * 64 + f4];
            uint2 hi, lo; split4(v, hi, lo);
            uint32_t a1 = (uint32_t)r * ROWB + (uint32_t)f4 * 8u;
            *(uint2*)(smc + SMO_BHI + a1) = hi;
            *(uint2*)(smc + SMO_BLO + a1) = lo;
        }
    }
    if (tid < R_) saS[tid] = pm_a[(size_t)pair * R_ + tid];
    __syncthreads();

    if (tid < MTILE)
        invS[tid] = 1.0f / fmaxf(sqrtf(partS[2 * tid] + partS[2 * tid + 1]), 1e-8f);
    __syncthreads();

    // ================= GEMM1: scores[128,64] = q_split . K_split^T =================
    // Warp owns rows 16*wid..16*wid+15, all 64 cols (8 n8-tiles).
    float acc[8][4];
    #pragma unroll
    for (int t = 0; t < 8; ++t)
        #pragma unroll
        for (int i = 0; i < 4; ++i) acc[t][i] = 0.f;

    const uint32_t aOff = ((uint32_t)(16 * wid + (lane & 15))) * ROWB + (uint32_t)(lane >> 4) * 16u;
    const uint32_t bOff = ((uint32_t)((lane & 7) + ((lane & 16) >> 1))) * ROWB +
                          (uint32_t)((lane >> 3) & 1) * 16u;

    #pragma unroll 1
    for (int p = 0; p < 3; ++p) {
        const uint32_t aBase = smb + (p == 2 ? SMO_ALO : SMO_AHI) + aOff;
        const uint32_t bBase = smb + (p == 1 ? SMO_BLO : SMO_BHI) + bOff;
        #pragma unroll
        for (int k = 0; k < 16; ++k) {
            uint32_t a[4];
            ldsm4(a, aBase + (uint32_t)k * 32u);
            #pragma unroll
            for (int g = 0; g < 4; ++g) {
                uint32_t bb[4];
                ldsm4(bb, bBase + (uint32_t)g * (16u * ROWB) + (uint32_t)k * 32u);
                mma16816(acc[2 * g + 0], a, bb + 0);
                mma16816(acc[2 * g + 1], a, bb + 2);
            }
        }
    }

    // ---- Epilogue1: w = scores * inv * a, re-split to bf16 A-fragments (registers) ----
    uint32_t ahi2[4][4], alo2[4][4];
    {
        const int r0 = 16 * wid + (lane >> 2);
        const float inv0 = invS[r0], inv1 = invS[r0 + 8];
        const int q2 = (lane & 3) * 2;
        #pragma unroll
        for (int kt = 0; kt < 4; ++kt) {
            #pragma unroll
            for (int hf = 0; hf < 2; ++hf) {
                int t = 2 * kt + hf;
                float2 av = *(const float2*)&saS[8 * t + q2];
                float w00 = acc[t][0] * inv0 * av.x, w01 = acc[t][1] * inv0 * av.y;
                float w10 = acc[t][2] * inv1 * av.x, w11 = acc[t][3] * inv1 * av.y;
                __nv_bfloat16 h00 = __float2bfloat16_rn(w00), h01 = __float2bfloat16_rn(w01);
                __nv_bfloat16 h10 = __float2bfloat16_rn(w10), h11 = __float2bfloat16_rn(w11);
                ahi2[kt][2 * hf + 0] = (uint32_t)__bfloat16_as_ushort(h00) |
                                       ((uint32_t)__bfloat16_as_ushort(h01) << 16);
                ahi2[kt][2 * hf + 1] = (uint32_t)__bfloat16_as_ushort(h10) |
                                       ((uint32_t)__bfloat16_as_ushort(h11) << 16);
                alo2[kt][2 * hf + 0] = packbf(w00 - __bfloat162float(h00),
                                              w01 - __bfloat162float(h01));
                alo2[kt][2 * hf + 1] = packbf(w10 - __bfloat162float(h10),
                                              w11 - __bfloat162float(h11));
            }
        }
    }
    __syncthreads();   // all warps done reading K from smem

    // ---- Load + split V into the (former K) B buffers ----
    {
        const int h  = wid & 1;
        const int wr = wid >> 1;
        const int f4 = h * 32 + lane;
        const float4* vg = (const float4*)pm_V + (size_t)pair * (R_ * D_ / 4);
        #pragma unroll 4
        for (int k = 0; k < 16; ++k) {
            int r = 4 * k + wr;
            float4 v = vg[(size_t)r * 64 + f4];
            uint2 hi, lo; split4(v, hi, lo);
            uint32_t a1 = (uint32_t)r * ROWB + (uint32_t)f4 * 8u;
            *(uint2*)(smc + SMO_BHI + a1) = hi;
            *(uint2*)(smc + SMO_BLO + a1) = lo;
        }
    }
    __syncthreads();

    // ================= GEMM2: mod[128,256] = W . V, N in 4 chunks of 64 =================
    const uint32_t vOff = ((uint32_t)(lane & 15)) * ROWB + (uint32_t)(lane >> 4) * 16u;
    const int r0 = 16 * wid + (lane >> 2);
    const int q2 = (lane & 3) * 2;
    const size_t g0base = ((size_t)(s * N_ + n0 + r0) * B_ + b) * D_;
    const size_t g1base = g0base + (size_t)8 * (B_ * D_);

    #pragma unroll 1
    for (int j = 0; j < 4; ++j) {
        #pragma unroll
        for (int t = 0; t < 8; ++t)
            #pragma unroll
            for (int i = 0; i < 4; ++i) acc[t][i] = 0.f;

        gemm2_pass(acc, ahi2, smb + SMO_BHI + vOff + (uint32_t)j * 128u);
        gemm2_pass(acc, alo2, smb + SMO_BHI + vOff + (uint32_t)j * 128u);
        gemm2_pass(acc, ahi2, smb + SMO_BLO + vOff + (uint32_t)j * 128u);

        // ---- Epilogue2: out = q * mod (q re-read from gmem, L2-resident) ----
        #pragma unroll
        for (int t = 0; t < 8; ++t) {
            int col = 64 * j + 8 * t + q2;
            float2 q0 = *(const float2*)(q + g0base + col);
            float2 q1 = *(const float2*)(q + g1base + col);
            float2 o0, o1;
            o0.x = q0.x * acc[t][0]; o0.y = q0.y * acc[t][1];
            o1.x = q1.x * acc[t][2]; o1.y = q1.y * acc[t][3];
            *(float2*)(out + g0base + col) = o0;
            *(float2*)(out + g1base + col) = o1;
        }
    }
}

extern "C" void kernel_launch(void* const* d_in, const int* in_sizes, int n_in,
                              void* d_out, int out_size)
{
    const float* q    = (const float*)d_in[0];
    const float* pm_K = (const float*)d_in[1];
    const float* pm_V = (const float*)d_in[2];
    const float* pm_a = (const float*)d_in[3];
    float* out = (float*)d_out;

    cudaFuncSetAttribute(ProceduralMemory_81535659147884_kernel,
                         cudaFuncAttributeMaxDynamicSharedMemorySize, SMEM_TOTAL);

    dim3 grid(BS_ * B_ * (N_ / MTILE));   // 2048 CTAs
    ProceduralMemory_81535659147884_kernel<<<grid, THREADS, SMEM_TOTAL>>>(
        q, pm_K, pm_V, pm_a, out);
}